// round 11
// baseline (speedup 1.0000x reference)
#include <cuda_runtime.h>

#define BB 64
#define SS 1024
#define DD 16
#define NSPLIT 4
#define TOK (BB * SS)

// Scratch (allocation-free rule: __device__ globals)
__device__ float4 g_part[NSPLIT * TOK]; // per-split partial (l, a0, a1, 0)
__device__ float  g_A[256];             // diag(g) @ (W1W2W3 + I)
__device__ float  g_csA[16];            // column sums of g_A
__device__ float  g_bA[16];             // b @ (W1W2W3+I) + bc
__device__ float  g_O[256];             // diag(g) @ Wo
__device__ float  g_csO[16];            // column sums of g_O
__device__ float  g_bO[16];             // b @ Wo + bo

__device__ __forceinline__ float ex2_approx(float x) {
    float y;
    asm("ex2.approx.f32 %0, %1;" : "=f"(y) : "f"(x));
    return y;
}

// ---------------------------------------------------------------------------
// Kernel A: inline-QKV attention, 4-way KV block split, 2 q-tokens/thread.
// Grid (3, NSPLIT, BB), 256 threads.
//   chunk 0..1 : attention for s in [chunk*512, chunk*512+512)
//   chunk 2    : (y==0,z==0) epilogue weight precompute; others exit.
// Each block computes its own KV quarter (1 token/thread, 64 FMA) and its
// own 2 Q tokens/thread (64 FMA) -- no qkv kernel, no g_q/g_kv globals.
// ---------------------------------------------------------------------------
__global__ void __launch_bounds__(256)
attn_kernel(const float* __restrict__ x,
            const float* __restrict__ Wq, const float* __restrict__ bq,
            const float* __restrict__ Wk, const float* __restrict__ bk,
            const float* __restrict__ Wv, const float* __restrict__ bv,
            const float* __restrict__ W1, const float* __restrict__ b1,
            const float* __restrict__ W2, const float* __restrict__ b2,
            const float* __restrict__ W3, const float* __restrict__ b3,
            const float* __restrict__ ln_g, const float* __restrict__ ln_b,
            const float* __restrict__ Wo, const float* __restrict__ bo)
{
    int tid = threadIdx.x;

    if (blockIdx.x == 2) {
        if (blockIdx.y != 0 || blockIdx.z != 0) return;
        // ------- precompute folded epilogue weights -------
        __shared__ float s1[256], s2[256], s3[256], s12[256];
        __shared__ float sA[256], sAraw[256], sO[256];
        __shared__ float sbp[16], sbc[16], sg[16], sb[16];
        int r = tid >> 4, c = tid & 15;
        s1[tid] = W1[tid]; s2[tid] = W2[tid]; s3[tid] = W3[tid];
        if (tid < 16) { sg[tid] = ln_g[tid]; sb[tid] = ln_b[tid]; }
        __syncthreads();

        float acc = 0.f;
        #pragma unroll
        for (int k = 0; k < 16; k++) acc = fmaf(s1[r*16+k], s2[k*16+c], acc);
        s12[tid] = acc;
        if (tid < 16) {                 // b1@W2 + b2
            float t = b2[tid];
            #pragma unroll
            for (int k = 0; k < 16; k++) t = fmaf(b1[k], s2[k*16+tid], t);
            sbp[tid] = t;
        }
        __syncthreads();

        float w123 = 0.f;
        #pragma unroll
        for (int k = 0; k < 16; k++) w123 = fmaf(s12[r*16+k], s3[k*16+c], w123);
        float A = w123 + (r == c ? 1.0f : 0.0f);   // residual folded in
        sAraw[tid] = A;
        sA[tid] = sg[r] * A;
        sO[tid] = sg[r] * Wo[tid];
        if (tid < 16) {                 // bc = (b1@W2+b2)@W3 + b3
            float t = b3[tid];
            #pragma unroll
            for (int k = 0; k < 16; k++) t = fmaf(sbp[k], s3[k*16+tid], t);
            sbc[tid] = t;
        }
        __syncthreads();

        g_A[tid] = sA[tid];
        g_O[tid] = sO[tid];
        if (tid < 16) {
            float cs = 0.f, bb = sbc[tid];
            float cso = 0.f, bb2 = bo[tid];
            #pragma unroll
            for (int i = 0; i < 16; i++) {
                cs  += sA[i*16+tid];
                bb   = fmaf(sb[i], sAraw[i*16+tid], bb);
                cso += sO[i*16+tid];
                bb2  = fmaf(sb[i], Wo[i*16+tid], bb2);
            }
            g_csA[tid] = cs;  g_bA[tid] = bb;
            g_csO[tid] = cso; g_bO[tid] = bb2;
        }
        return;
    }

    // ------- attention block -------
    __shared__ float4 skv[256];     // KV quarter (4 KB)
    __shared__ float sw[102];       // Wq[32] Wk[32] Wv[32] bq bk bv

    int b     = blockIdx.z;
    int split = blockIdx.y;
    int chunk = blockIdx.x;

    int idx0 = b * SS + chunk * 512 + tid;     // q token A
    int idx1 = idx0 + 256;                     // q token B
    int tkv  = b * SS + split * 256 + tid;     // kv token

    // Hoist all x loads (12 independent LDG.128) above the weight prologue
    const float4* xk = reinterpret_cast<const float4*>(x + tkv  * DD);
    const float4* xa = reinterpret_cast<const float4*>(x + idx0 * DD);
    const float4* xb = reinterpret_cast<const float4*>(x + idx1 * DD);
    float4 k0v = xk[0], k1v = xk[1], k2v = xk[2], k3v = xk[3];
    float4 a0v = xa[0], a1v = xa[1], a2v = xa[2], a3v = xa[3];
    float4 b0v = xb[0], b1v = xb[1], b2v = xb[2], b3v = xb[3];

    if (tid < 32)        sw[tid] = Wq[tid];
    else if (tid < 64)   sw[tid] = Wk[tid - 32];
    else if (tid < 96)   sw[tid] = Wv[tid - 64];
    else if (tid < 98)   sw[tid] = bq[tid - 96];
    else if (tid < 100)  sw[tid] = bk[tid - 98];
    else if (tid < 102)  sw[tid] = bv[tid - 100];
    __syncthreads();

    // KV for this thread's token (64 FMA)
    {
        float xe[16] = {k0v.x,k0v.y,k0v.z,k0v.w, k1v.x,k1v.y,k1v.z,k1v.w,
                        k2v.x,k2v.y,k2v.z,k2v.w, k3v.x,k3v.y,k3v.z,k3v.w};
        float k0 = sw[98], k1 = sw[99], v0 = sw[100], v1 = sw[101];
        #pragma unroll
        for (int i = 0; i < 16; i++) {
            float xi = xe[i];
            k0 = fmaf(xi, sw[32+i*2+0], k0);
            k1 = fmaf(xi, sw[32+i*2+1], k1);
            v0 = fmaf(xi, sw[64+i*2+0], v0);
            v1 = fmaf(xi, sw[64+i*2+1], v1);
        }
        skv[tid] = make_float4(k0, k1, v0, v1);
    }

    // Q for the two owned tokens (64 FMA), fold 0.25*log2e
    const float SC = 0.25f * 1.4426950408889634f;
    float qa0 = sw[96], qa1 = sw[97], qb0 = sw[96], qb1 = sw[97];
    {
        float xA[16] = {a0v.x,a0v.y,a0v.z,a0v.w, a1v.x,a1v.y,a1v.z,a1v.w,
                        a2v.x,a2v.y,a2v.z,a2v.w, a3v.x,a3v.y,a3v.z,a3v.w};
        float xB[16] = {b0v.x,b0v.y,b0v.z,b0v.w, b1v.x,b1v.y,b1v.z,b1v.w,
                        b2v.x,b2v.y,b2v.z,b2v.w, b3v.x,b3v.y,b3v.z,b3v.w};
        #pragma unroll
        for (int i = 0; i < 16; i++) {
            qa0 = fmaf(xA[i], sw[i*2+0], qa0);
            qa1 = fmaf(xA[i], sw[i*2+1], qa1);
            qb0 = fmaf(xB[i], sw[i*2+0], qb0);
            qb1 = fmaf(xB[i], sw[i*2+1], qb1);
        }
        qa0 *= SC; qa1 *= SC; qb0 *= SC; qb1 *= SC;
    }
    __syncthreads();

    float l0 = 0.f, a00 = 0.f, a01 = 0.f;
    float l1 = 0.f, a10 = 0.f, a11 = 0.f;

    #pragma unroll 8
    for (int t = 0; t < 256; t++) {
        float4 kv = skv[t];
        float d0 = fmaf(qa1, kv.y, qa0 * kv.x);
        float d1 = fmaf(qb1, kv.y, qb0 * kv.x);
        float p0 = ex2_approx(d0);
        float p1 = ex2_approx(d1);
        l0 += p0;                    l1 += p1;
        a00 = fmaf(p0, kv.z, a00);   a10 = fmaf(p1, kv.z, a10);
        a01 = fmaf(p0, kv.w, a01);   a11 = fmaf(p1, kv.w, a11);
    }

    g_part[split * TOK + idx0] = make_float4(l0, a00, a01, 0.f);
    g_part[split * TOK + idx1] = make_float4(l1, a10, a11, 0.f);
}

// ---------------------------------------------------------------------------
// Kernel B: epilogue, 1 thread/token, LN-folded weights, hoisted loads.
// ---------------------------------------------------------------------------
__global__ void __launch_bounds__(256)
epilogue_kernel(const float* __restrict__ x,
                const float* __restrict__ Wu, const float* __restrict__ bu,
                float* __restrict__ out)
{
    __shared__ __align__(16) float sA[256], sO[256], sWu[32];
    __shared__ float sbu[16], scsA[16], sbA[16], scsO[16], sbO[16];

    int tid = threadIdx.x;
    int idx = blockIdx.x * 256 + tid;

    // Hoisted: 4 partial loads + 4 x loads (8 LDG.128 in flight)
    float4 p0 = g_part[0 * TOK + idx];
    float4 p1 = g_part[1 * TOK + idx];
    float4 p2 = g_part[2 * TOK + idx];
    float4 p3 = g_part[3 * TOK + idx];
    const float4* xp = reinterpret_cast<const float4*>(x + idx * DD);
    float4 xv0 = xp[0], xv1 = xp[1], xv2 = xp[2], xv3 = xp[3];

    sA[tid] = g_A[tid]; sO[tid] = g_O[tid];
    if (tid < 32) sWu[tid] = Wu[tid];
    if (tid < 16) {
        sbu[tid] = bu[tid];
        scsA[tid] = g_csA[tid]; sbA[tid] = g_bA[tid];
        scsO[tid] = g_csO[tid]; sbO[tid] = g_bO[tid];
    }
    __syncthreads();

    float l  = p0.x + p1.x + p2.x + p3.x;
    float a0 = p0.y + p1.y + p2.y + p3.y;
    float a1 = p0.z + p1.z + p2.z + p3.z;
    float inv = 1.0f / l;
    float c0 = a0 * inv, c1 = a1 * inv;

    float xr[16] = {xv0.x, xv0.y, xv0.z, xv0.w, xv1.x, xv1.y, xv1.z, xv1.w,
                    xv2.x, xv2.y, xv2.z, xv2.w, xv3.x, xv3.y, xv3.z, xv3.w};

    // u = ctx @ Wu + bu + x
    float u[16];
    #pragma unroll
    for (int i = 0; i < 16; i++)
        u[i] = fmaf(c0, sWu[i], fmaf(c1, sWu[16 + i], sbu[i])) + xr[i];

    // LN stats of u
    float su = 0.f, s2 = 0.f;
    #pragma unroll
    for (int i = 0; i < 16; i++) { su += u[i]; s2 = fmaf(u[i], u[i], s2); }
    float mu = su * (1.0f / 16.0f);
    float r  = rsqrtf(fmaf(-mu, mu, s2 * (1.0f / 16.0f)) + 1e-5f);

    // f = r*(u@A' - mu*csA) + bA
    float f[16];
    {
        float acc[16];
        #pragma unroll
        for (int j = 0; j < 16; j++) acc[j] = 0.f;
        #pragma unroll
        for (int i = 0; i < 16; i++) {
            float hv = u[i];
            const float4* wr = reinterpret_cast<const float4*>(sA + i * 16);
            #pragma unroll
            for (int j4 = 0; j4 < 4; j4++) {
                float4 w = wr[j4];
                acc[4*j4+0] = fmaf(hv, w.x, acc[4*j4+0]);
                acc[4*j4+1] = fmaf(hv, w.y, acc[4*j4+1]);
                acc[4*j4+2] = fmaf(hv, w.z, acc[4*j4+2]);
                acc[4*j4+3] = fmaf(hv, w.w, acc[4*j4+3]);
            }
        }
        #pragma unroll
        for (int j = 0; j < 16; j++)
            f[j] = fmaf(r, fmaf(-mu, scsA[j], acc[j]), sbA[j]);
    }

    // LN stats of f
    float sf = 0.f, sf2 = 0.f;
    #pragma unroll
    for (int i = 0; i < 16; i++) { sf += f[i]; sf2 = fmaf(f[i], f[i], sf2); }
    float mu2 = sf * (1.0f / 16.0f);
    float r2  = rsqrtf(fmaf(-mu2, mu2, sf2 * (1.0f / 16.0f)) + 1e-5f);

    // out = r2*(f@O' - mu2*csO) + bO
    float o[16];
    {
        float acc[16];
        #pragma unroll
        for (int j = 0; j < 16; j++) acc[j] = 0.f;
        #pragma unroll
        for (int i = 0; i < 16; i++) {
            float hv = f[i];
            const float4* wr = reinterpret_cast<const float4*>(sO + i * 16);
            #pragma unroll
            for (int j4 = 0; j4 < 4; j4++) {
                float4 w = wr[j4];
                acc[4*j4+0] = fmaf(hv, w.x, acc[4*j4+0]);
                acc[4*j4+1] = fmaf(hv, w.y, acc[4*j4+1]);
                acc[4*j4+2] = fmaf(hv, w.z, acc[4*j4+2]);
                acc[4*j4+3] = fmaf(hv, w.w, acc[4*j4+3]);
            }
        }
        #pragma unroll
        for (int j = 0; j < 16; j++)
            o[j] = fmaf(r2, fmaf(-mu2, scsO[j], acc[j]), sbO[j]);
    }

    float4* op = reinterpret_cast<float4*>(out + idx * DD);
    #pragma unroll
    for (int c4 = 0; c4 < 4; c4++)
        op[c4] = make_float4(o[4*c4+0], o[4*c4+1], o[4*c4+2], o[4*c4+3]);
}

// ---------------------------------------------------------------------------
extern "C" void kernel_launch(void* const* d_in, const int* in_sizes, int n_in,
                              void* d_out, int out_size)
{
    const float* x    = (const float*)d_in[0];
    const float* Wq   = (const float*)d_in[1];
    const float* bq   = (const float*)d_in[2];
    const float* Wk   = (const float*)d_in[3];
    const float* bk   = (const float*)d_in[4];
    const float* Wv   = (const float*)d_in[5];
    const float* bv   = (const float*)d_in[6];
    const float* Wu   = (const float*)d_in[7];
    const float* bu   = (const float*)d_in[8];
    const float* ln_g = (const float*)d_in[9];
    const float* ln_b = (const float*)d_in[10];
    const float* W1   = (const float*)d_in[11];
    const float* b1   = (const float*)d_in[12];
    const float* W2   = (const float*)d_in[13];
    const float* b2   = (const float*)d_in[14];
    const float* W3   = (const float*)d_in[15];
    const float* b3   = (const float*)d_in[16];
    const float* Wo   = (const float*)d_in[17];
    const float* bo   = (const float*)d_in[18];
    float* out = (float*)d_out;

    dim3 agrid(3, NSPLIT, BB);
    attn_kernel<<<agrid, 256>>>(x, Wq, bq, Wk, bk, Wv, bv,
                                W1, b1, W2, b2, W3, b3, ln_g, ln_b, Wo, bo);

    epilogue_kernel<<<TOK / 256, 256>>>(x, Wu, bu, out);
}